// round 6
// baseline (speedup 1.0000x reference)
#include <cuda_runtime.h>
#include <math.h>

#define BB 20
#define LL 20
#define VV 100000
#define NSTEP (2 * LL - 1)          // 39 wavefronts
#define ROWS_PAD (NSTEP + LL)       // j in [-(LL-1), NSTEP-1] -> 58 padded rows

__device__ __align__(16) float g_calcs[BB];
__device__ int g_count = 0;         // reset by last block each launch -> replay-safe

__global__ __launch_bounds__(LL * LL, 1)
void calcs_fused(const float* __restrict__ tp,
                 const int*   __restrict__ hl,
                 float* __restrict__ out) {
    // ACp[(j+LL-1)*LL + k] = (a, c); rows outside j in [0,LL) are zeros
    __shared__ float2 ACp[ROWS_PAD * LL];
    __shared__ int   len_s;
    __shared__ float final_s;

    const int b = blockIdx.x;
    const int t = threadIdx.x;
    const int j = t / LL;
    const int k = t - j * LL;

    if (t == 0) final_s = 0.0f;

    // zero-fill the 760 padding entries (rows 0..18 and 39..57), <=2 per thread
    for (int i = t; i < (ROWS_PAD - LL) * LL; i += LL * LL) {
        int idx = (i < (LL - 1) * LL) ? i : i + LL * LL;   // skip real rows 19..38
        ACp[idx] = make_float2(0.0f, 0.0f);
    }

    // labels (same 128B line -> L1 broadcast), then the dependent gather
    const int hj = hl[b * LL + j];
    const int hk = hl[b * LL + k];
    const float m2 = (hj >= 0 && hk >= 0) ? 1.0f : 0.0f;
    const int idx = hk < 0 ? 0 : (hk >= VV ? VV - 1 : hk);

    const float p = tp[(size_t)b * (LL * VV) + (size_t)j * VV + idx];
    const float a = m2 * p;
    ACp[(j + LL - 1) * LL + k] = make_float2(a, m2 - a);

    // barrier + popcount: len = #valid labels
    int cnt = __syncthreads_count((j == 0 && hk >= 0) ? 1 : 0);
    if (t == 0) len_s = cnt;
    __syncthreads();

    // ---- systolic wavefront DP on warp 0: lane k = column k ----
    if (t < 32) {
        const int lane = t;
        const int lenm1 = len_s - 1;
        const int src = (lane + 31) & 31;        // lane-1 (lane 0 <- lane 31, which stays 0)
        // lane's ACp base for step 0 (j = -lane); clamp keeps lanes>=20 in-bounds
        int base = (LL - 1 - lane) * LL + lane;
        if (base < 0) base = lane;               // zero rows for lanes 20..31
        const float2* __restrict__ acp = &ACp[base];

        float val = 0.0f;        // own value (row j-1 at step start)
        float leftPrev = 0.0f;   // neighbor value from 2 steps ago = diag

        float final_v = 0.0f;

        #pragma unroll
        for (int s = 0; s < NSTEP; s++) {
            float nl = __shfl_sync(0xFFFFFFFFu, val, src);   // neighbor val @ step s-1
            float2 ac = acp[s * LL];
            float aa = (lane < LL) ? ac.x : 0.0f;            // off critical path
            float cc = (lane < LL) ? ac.y : 0.0f;
            float dd = fmaf(aa, leftPrev, aa);               // a*(diag+1), off chain
            float up = val;
            val = fmaf(cc, fmaxf(nl, up), dd);               // chain: shfl->fmax->ffma
            leftPrev = nl;
            if (lane == lenm1 && (s - lane) == lenm1) final_v = val;
        }

        if (lane == lenm1 && lenm1 >= 0) final_s = final_v;
        __syncwarp();

        if (lane == 0) {
            const int len = len_s;
            g_calcs[b] = -logf(final_s / (float)len);
            __threadfence();
            if (atomicAdd(&g_count, 1) == BB - 1) {
                __threadfence();
                // deterministic fixed-order reduction, vectorized loads
                const float4* __restrict__ gc = (const float4*)g_calcs;
                float s0 = 0.0f;
                #pragma unroll
                for (int i = 0; i < BB / 4; i++) {
                    float4 v = gc[i];
                    s0 += ((v.x + v.y) + (v.z + v.w));
                }
                out[0] = s0 / (float)BB;
                g_count = 0;    // re-arm for next graph replay
            }
        }
    }
}

extern "C" void kernel_launch(void* const* d_in, const int* in_sizes, int n_in,
                              void* d_out, int out_size) {
    const float* tp = (const float*)d_in[0];   // topic_prob [B, L, V] f32
    const int*   hl = (const int*)d_in[1];     // hard_label [B, L] i32
    float* out = (float*)d_out;
    calcs_fused<<<BB, LL * LL>>>(tp, hl, out);
}